// round 1
// baseline (speedup 1.0000x reference)
#include <cuda_runtime.h>
#include <cstdint>

// Problem constants
#define NT 8192      // tokens
#define DIM 1024     // model dim

// ---------------- static device scratch (no allocs allowed) ----------------
__device__ float d_qc[(size_t)NT * DIM];          // q_hat -> centered*c
__device__ float d_kc[(size_t)NT * DIM];          // k_hat -> centered
__device__ float d_g [(size_t)NT * DIM];          // g = x@Wg
__device__ float d_S [(size_t)NT * NT];           // scores / attn (256 MB)
__device__ float d_part[32 * DIM];                // column partial sums
__device__ float d_colred[3 * DIM];               // [mq | mk | gsum]
__device__ float d_m[NT];                         // m = x@Wm_w + b
__device__ float d_gate[NT];                      // softmax(m) over tokens

// ---------------- reduction helpers ----------------
__device__ __forceinline__ float warpMax(float v) {
    #pragma unroll
    for (int o = 16; o > 0; o >>= 1) v = fmaxf(v, __shfl_xor_sync(0xffffffffu, v, o));
    return v;
}
__device__ __forceinline__ float warpSum(float v) {
    #pragma unroll
    for (int o = 16; o > 0; o >>= 1) v += __shfl_xor_sync(0xffffffffu, v, o);
    return v;
}

// ---------------- tiled SGEMM ----------------
// C[M,Nn] = A[M,K] @ B  (BT=false: B is [K,Nn] row-major; BT=true: B is [Nn,K] row-major, C=A@B^T)
// EPI=true adds gate[row]*gsum[col] + xres[row,col]
template <bool BT, bool EPI>
__global__ __launch_bounds__(256, 2)
void sgemm_kernel(const float* __restrict__ A, const float* __restrict__ B,
                  float* __restrict__ C, int M, int Nn, int K,
                  const float* __restrict__ gate, const float* __restrict__ gsum,
                  const float* __restrict__ xres)
{
    constexpr int BM = 128, BN = 128, BK = 16, TM = 8, TN = 8;
    __shared__ float As[BK][BM + 4];
    __shared__ float Bs[BK][BN + 4];

    const int tid  = threadIdx.x;
    const int cRow = blockIdx.y;
    const int cCol = blockIdx.x;
    const int tCol = tid & 15;        // 0..15
    const int tRow = tid >> 4;        // 0..15

    // A-tile (and B-tile when BT) loader indices: 64 rows x 16 cols per pass
    const int aRow = tid >> 2;            // 0..63
    const int aCol = (tid & 3) * 4;       // 0,4,8,12
    // B-tile loader (NN): 8 rows x 128 cols per pass
    const int bRow = tid >> 5;            // 0..7
    const int bCol = (tid & 31) * 4;      // 0..124

    const float* Aptr = A + (size_t)cRow * BM * K;
    const float* Bptr = BT ? (B + (size_t)cCol * BN * K)
                           : (B + (size_t)cCol * BN);

    float acc[TM][TN];
    #pragma unroll
    for (int i = 0; i < TM; i++)
        #pragma unroll
        for (int j = 0; j < TN; j++) acc[i][j] = 0.0f;

    float rm[TM], rn[TN];

    for (int k0 = 0; k0 < K; k0 += BK) {
        // load A tile (transposed into As[k][m])
        #pragma unroll
        for (int off = 0; off < BM; off += 64) {
            float4 v = *reinterpret_cast<const float4*>(Aptr + (size_t)(aRow + off) * K + k0 + aCol);
            As[aCol + 0][aRow + off] = v.x;
            As[aCol + 1][aRow + off] = v.y;
            As[aCol + 2][aRow + off] = v.z;
            As[aCol + 3][aRow + off] = v.w;
        }
        if (BT) {
            #pragma unroll
            for (int off = 0; off < BN; off += 64) {
                float4 v = *reinterpret_cast<const float4*>(Bptr + (size_t)(aRow + off) * K + k0 + aCol);
                Bs[aCol + 0][aRow + off] = v.x;
                Bs[aCol + 1][aRow + off] = v.y;
                Bs[aCol + 2][aRow + off] = v.z;
                Bs[aCol + 3][aRow + off] = v.w;
            }
        } else {
            #pragma unroll
            for (int off = 0; off < BK; off += 8) {
                float4 v = *reinterpret_cast<const float4*>(Bptr + (size_t)(bRow + off + k0) * Nn + bCol);
                *reinterpret_cast<float4*>(&Bs[bRow + off][bCol]) = v;
            }
        }
        __syncthreads();

        #pragma unroll
        for (int kk = 0; kk < BK; kk++) {
            #pragma unroll
            for (int i = 0; i < TM; i += 4)
                *reinterpret_cast<float4*>(&rm[i]) =
                    *reinterpret_cast<const float4*>(&As[kk][tRow * TM + i]);
            #pragma unroll
            for (int j = 0; j < TN; j += 4)
                *reinterpret_cast<float4*>(&rn[j]) =
                    *reinterpret_cast<const float4*>(&Bs[kk][tCol * TN + j]);
            #pragma unroll
            for (int i = 0; i < TM; i++)
                #pragma unroll
                for (int j = 0; j < TN; j++)
                    acc[i][j] = fmaf(rm[i], rn[j], acc[i][j]);
        }
        __syncthreads();
    }

    const int rowBase = cRow * BM + tRow * TM;
    const int colBase = cCol * BN + tCol * TN;
    #pragma unroll
    for (int i = 0; i < TM; i++) {
        float grow = 0.0f;
        if (EPI) grow = gate[rowBase + i];
        #pragma unroll
        for (int j = 0; j < TN; j += 4) {
            float4 v = make_float4(acc[i][j], acc[i][j + 1], acc[i][j + 2], acc[i][j + 3]);
            if (EPI) {
                float4 gs = *reinterpret_cast<const float4*>(&gsum[colBase + j]);
                float4 xr = *reinterpret_cast<const float4*>(
                    &xres[(size_t)(rowBase + i) * Nn + colBase + j]);
                v.x += grow * gs.x + xr.x;
                v.y += grow * gs.y + xr.y;
                v.z += grow * gs.z + xr.z;
                v.w += grow * gs.w + xr.w;
            }
            *reinterpret_cast<float4*>(&C[(size_t)(rowBase + i) * Nn + colBase + j]) = v;
        }
    }
}

// ---------------- m = x @ Wm_w + b (one warp per row) ----------------
__global__ __launch_bounds__(256)
void mvec_kernel(const float* __restrict__ x, const float* __restrict__ w,
                 const float* __restrict__ b, float* __restrict__ m)
{
    const int row  = blockIdx.x * 8 + (threadIdx.x >> 5);
    const int lane = threadIdx.x & 31;
    const float* xr = x + (size_t)row * DIM;
    float s = 0.0f;
    #pragma unroll
    for (int k = lane * 4; k < DIM; k += 128) {
        float4 xv = *reinterpret_cast<const float4*>(xr + k);
        float4 wv = *reinterpret_cast<const float4*>(w + k);
        s += xv.x * wv.x + xv.y * wv.y + xv.z * wv.z + xv.w * wv.w;
    }
    s = warpSum(s);
    if (lane == 0) m[row] = s + b[0];
}

// ---------------- column partial sums (deterministic 2-stage) ----------------
__global__ void colsum_partial(const float* __restrict__ A, float* __restrict__ part)
{
    const int col   = blockIdx.x * blockDim.x + threadIdx.x;  // DIM cols
    const int chunk = blockIdx.y;                             // 32 chunks
    const int r0    = chunk * (NT / 32);
    float s = 0.0f;
    for (int r = 0; r < NT / 32; r++) s += A[(size_t)(r0 + r) * DIM + col];
    part[chunk * DIM + col] = s;
}
__global__ void colsum_final(const float* __restrict__ part, float* __restrict__ out, float scale)
{
    const int col = blockIdx.x * blockDim.x + threadIdx.x;
    float s = 0.0f;
    #pragma unroll
    for (int c = 0; c < 32; c++) s += part[c * DIM + col];
    out[col] = s * scale;
}

// ---------------- gate = softmax(m) over all tokens (single block) ----------------
__global__ __launch_bounds__(1024)
void gate_kernel(const float* __restrict__ m, float* __restrict__ gate)
{
    __shared__ float red[32];
    const int tid = threadIdx.x, lane = tid & 31, wid = tid >> 5;
    float v[8];
    float vmax = -INFINITY;
    #pragma unroll
    for (int k = 0; k < 8; k++) { v[k] = m[tid + k * 1024]; vmax = fmaxf(vmax, v[k]); }
    vmax = warpMax(vmax);
    if (lane == 0) red[wid] = vmax;
    __syncthreads();
    float rmax = red[0];
    #pragma unroll
    for (int c = 1; c < 32; c++) rmax = fmaxf(rmax, red[c]);
    float s = 0.0f;
    #pragma unroll
    for (int k = 0; k < 8; k++) { v[k] = __expf(v[k] - rmax); s += v[k]; }
    s = warpSum(s);
    __syncthreads();
    if (lane == 0) red[wid] = s;
    __syncthreads();
    float tot = 0.0f;
    #pragma unroll
    for (int c = 0; c < 32; c++) tot += red[c];
    const float inv = 1.0f / tot;
    #pragma unroll
    for (int k = 0; k < 8; k++) gate[tid + k * 1024] = v[k] * inv;
}

// ---------------- center: qc=(qhat-mq)*c ; kc=khat-mk ----------------
__global__ __launch_bounds__(256)
void center_kernel(float* __restrict__ qc, float* __restrict__ kc,
                   const float* __restrict__ colred, const float* __restrict__ cptr)
{
    const float c = *cptr;
    const size_t i4   = (size_t)blockIdx.x * blockDim.x + threadIdx.x;  // float4 index
    const int    col4 = (int)(i4 & (DIM / 4 - 1));
    float4 mq = reinterpret_cast<const float4*>(colred)[col4];
    float4 mk = reinterpret_cast<const float4*>(colred + DIM)[col4];
    float4 q = reinterpret_cast<float4*>(qc)[i4];
    q.x = (q.x - mq.x) * c; q.y = (q.y - mq.y) * c;
    q.z = (q.z - mq.z) * c; q.w = (q.w - mq.w) * c;
    reinterpret_cast<float4*>(qc)[i4] = q;
    float4 k = reinterpret_cast<float4*>(kc)[i4];
    k.x -= mk.x; k.y -= mk.y; k.z -= mk.z; k.w -= mk.w;
    reinterpret_cast<float4*>(kc)[i4] = k;
}

// ---------------- row softmax of S in place (one block per row) ----------------
__global__ __launch_bounds__(256)
void softmax_kernel(float* __restrict__ S)
{
    __shared__ float buf[NT];
    __shared__ float red[8];
    const int tid = threadIdx.x, lane = tid & 31, wid = tid >> 5;
    float* Sr = S + (size_t)blockIdx.x * NT;

    float vmax = -INFINITY;
    #pragma unroll
    for (int k = 0; k < 8; k++) {
        int i = (tid + k * 256) * 4;
        float4 v = *reinterpret_cast<const float4*>(Sr + i);
        *reinterpret_cast<float4*>(buf + i) = v;
        vmax = fmaxf(vmax, fmaxf(fmaxf(v.x, v.y), fmaxf(v.z, v.w)));
    }
    vmax = warpMax(vmax);
    if (lane == 0) red[wid] = vmax;
    __syncthreads();
    float rmax = red[0];
    #pragma unroll
    for (int c = 1; c < 8; c++) rmax = fmaxf(rmax, red[c]);

    float ssum = 0.0f;
    #pragma unroll
    for (int k = 0; k < 8; k++) {
        int i = (tid + k * 256) * 4;
        float4 v = *reinterpret_cast<float4*>(buf + i);
        v.x = __expf(v.x - rmax); v.y = __expf(v.y - rmax);
        v.z = __expf(v.z - rmax); v.w = __expf(v.w - rmax);
        ssum += v.x + v.y + v.z + v.w;
        *reinterpret_cast<float4*>(buf + i) = v;
    }
    ssum = warpSum(ssum);
    __syncthreads();
    if (lane == 0) red[wid] = ssum;
    __syncthreads();
    float tot = 0.0f;
    #pragma unroll
    for (int c = 0; c < 8; c++) tot += red[c];
    const float inv = 1.0f / tot;
    #pragma unroll
    for (int k = 0; k < 8; k++) {
        int i = (tid + k * 256) * 4;
        float4 v = *reinterpret_cast<float4*>(buf + i);
        v.x *= inv; v.y *= inv; v.z *= inv; v.w *= inv;
        *reinterpret_cast<float4*>(Sr + i) = v;
    }
}

// ---------------- host launch ----------------
extern "C" void kernel_launch(void* const* d_in, const int* in_sizes, int n_in,
                              void* d_out, int out_size)
{
    const float* x    = (const float*)d_in[0];
    const float* Wq   = (const float*)d_in[1];
    const float* Wk   = (const float*)d_in[2];
    const float* Wg   = (const float*)d_in[3];
    const float* Wm_w = (const float*)d_in[4];
    const float* Wm_b = (const float*)d_in[5];
    const float* cs   = (const float*)d_in[6];
    float* out = (float*)d_out;

    float *qc, *kc, *g, *S, *part, *colred, *mv, *gate;
    cudaGetSymbolAddress((void**)&qc, d_qc);
    cudaGetSymbolAddress((void**)&kc, d_kc);
    cudaGetSymbolAddress((void**)&g,  d_g);
    cudaGetSymbolAddress((void**)&S,  d_S);
    cudaGetSymbolAddress((void**)&part, d_part);
    cudaGetSymbolAddress((void**)&colred, d_colred);
    cudaGetSymbolAddress((void**)&mv, d_m);
    cudaGetSymbolAddress((void**)&gate, d_gate);

    float* mq   = colred;            // [DIM]
    float* mk   = colred + DIM;      // [DIM]
    float* gsum = colred + 2 * DIM;  // [DIM]

    const dim3 gProj(DIM / 128, NT / 128);   // (8, 64)
    const dim3 gS(NT / 128, NT / 128);       // (64, 64)

    // 1) projections
    sgemm_kernel<false, false><<<gProj, 256>>>(x, Wq, qc, NT, DIM, DIM, nullptr, nullptr, nullptr);
    sgemm_kernel<false, false><<<gProj, 256>>>(x, Wk, kc, NT, DIM, DIM, nullptr, nullptr, nullptr);
    sgemm_kernel<false, false><<<gProj, 256>>>(x, Wg, g,  NT, DIM, DIM, nullptr, nullptr, nullptr);

    // 2) m = x@Wm_w + b ; gate = softmax(m)
    mvec_kernel<<<NT / 8, 256>>>(x, Wm_w, Wm_b, mv);
    gate_kernel<<<1, 1024>>>(mv, gate);

    // 3) column reductions: mean(q_hat), mean(k_hat), colsum(g)
    colsum_partial<<<dim3(DIM / 256, 32), 256>>>(qc, part);
    colsum_final<<<DIM / 256, 256>>>(part, mq, 1.0f / NT);
    colsum_partial<<<dim3(DIM / 256, 32), 256>>>(kc, part);
    colsum_final<<<DIM / 256, 256>>>(part, mk, 1.0f / NT);
    colsum_partial<<<dim3(DIM / 256, 32), 256>>>(g, part);
    colsum_final<<<DIM / 256, 256>>>(part, gsum, 1.0f);

    // 4) center (fold scale c into q)
    center_kernel<<<(NT * (DIM / 4)) / 256, 256>>>(qc, kc, colred, cs);

    // 5) S = qc @ kc^T  (already scaled by c)
    sgemm_kernel<true, false><<<gS, 256>>>(qc, kc, S, NT, NT, DIM, nullptr, nullptr, nullptr);

    // 6) row softmax in place
    softmax_kernel<<<NT, 256>>>(S);

    // 7) out = attn @ g + gate[i]*gsum[j] + x
    sgemm_kernel<false, true><<<gProj, 256>>>(S, g, out, NT, DIM, NT, gate, gsum, x);
}

// round 4
// speedup vs baseline: 2.2177x; 2.2177x over previous
#include <cuda_runtime.h>
#include <cuda_bf16.h>
#include <cstdint>

#define NT 8192      // tokens
#define DIM 1024     // model dim

// ---------------- static device scratch (no allocs allowed) ----------------
__device__ float d_qc[(size_t)NT * DIM];
__device__ float d_kc[(size_t)NT * DIM];
__device__ float d_g [(size_t)NT * DIM];
__device__ float d_gT[(size_t)NT * DIM];          // g transposed [DIM, NT]
__device__ float d_WT[(size_t)3 * DIM * DIM];     // WqT | WkT | WgT
__device__ float d_S [(size_t)NT * NT];           // scores / attn (256 MB)
__device__ float d_part[32 * DIM];
__device__ float d_colred[3 * DIM];               // [mq | mk | gsum]
__device__ float d_m[NT];
__device__ float d_gate[NT];

// ---------------- small helpers ----------------
__device__ __forceinline__ float warpMax(float v) {
    #pragma unroll
    for (int o = 16; o > 0; o >>= 1) v = fmaxf(v, __shfl_xor_sync(0xffffffffu, v, o));
    return v;
}
__device__ __forceinline__ float warpSum(float v) {
    #pragma unroll
    for (int o = 16; o > 0; o >>= 1) v += __shfl_xor_sync(0xffffffffu, v, o);
    return v;
}
__device__ __forceinline__ uint32_t smem_u32(const void* p) {
    uint32_t a;
    asm("{ .reg .u64 t; cvta.to.shared.u64 t, %1; cvt.u32.u64 %0, t; }" : "=r"(a) : "l"(p));
    return a;
}

// ---------------- mma.sync wrappers (base ISA — no 'a' features) ----------------
__device__ __forceinline__ void ldsm_x4(uint32_t& r0, uint32_t& r1, uint32_t& r2, uint32_t& r3,
                                        uint32_t addr) {
    asm volatile("ldmatrix.sync.aligned.m8n8.x4.shared.b16 {%0,%1,%2,%3}, [%4];"
                 : "=r"(r0), "=r"(r1), "=r"(r2), "=r"(r3) : "r"(addr));
}
__device__ __forceinline__ void ldsm_x2(uint32_t& r0, uint32_t& r1, uint32_t addr) {
    asm volatile("ldmatrix.sync.aligned.m8n8.x2.shared.b16 {%0,%1}, [%2];"
                 : "=r"(r0), "=r"(r1) : "r"(addr));
}
__device__ __forceinline__ void mma_bf16(float* c, const uint32_t* a, const uint32_t* b) {
    asm volatile("mma.sync.aligned.m16n8k16.row.col.f32.bf16.bf16.f32 "
                 "{%0,%1,%2,%3}, {%4,%5,%6,%7}, {%8,%9}, {%0,%1,%2,%3};"
                 : "+f"(c[0]), "+f"(c[1]), "+f"(c[2]), "+f"(c[3])
                 : "r"(a[0]), "r"(a[1]), "r"(a[2]), "r"(a[3]), "r"(b[0]), "r"(b[1]));
}

// smem tile layout: 128 rows x 32 bf16 (64 B per row); 16B unit c in 0..3
// swizzled unit: u = c ^ ((row>>1)&3)  -> conflict-free for STS.128 and ldmatrix
__device__ __forceinline__ uint32_t sw_addr(uint32_t base, int row, int c) {
    return base + (uint32_t)(row * 64) + (uint32_t)((c ^ ((row >> 1) & 3)) << 4);
}

// fp32x8 -> bf16 hi (uint4) + bf16 lo (uint4)
__device__ __forceinline__ void cvt_split(const float4& a, const float4& b,
                                          uint4& hi, uint4& lo) {
    __nv_bfloat162 h01 = __float22bfloat162_rn(make_float2(a.x, a.y));
    __nv_bfloat162 h23 = __float22bfloat162_rn(make_float2(a.z, a.w));
    __nv_bfloat162 h45 = __float22bfloat162_rn(make_float2(b.x, b.y));
    __nv_bfloat162 h67 = __float22bfloat162_rn(make_float2(b.z, b.w));
    __nv_bfloat162 l01 = __float22bfloat162_rn(
        make_float2(a.x - __low2float(h01), a.y - __high2float(h01)));
    __nv_bfloat162 l23 = __float22bfloat162_rn(
        make_float2(a.z - __low2float(h23), a.w - __high2float(h23)));
    __nv_bfloat162 l45 = __float22bfloat162_rn(
        make_float2(b.x - __low2float(h45), b.y - __high2float(h45)));
    __nv_bfloat162 l67 = __float22bfloat162_rn(
        make_float2(b.z - __low2float(h67), b.w - __high2float(h67)));
    hi = make_uint4(*reinterpret_cast<uint32_t*>(&h01), *reinterpret_cast<uint32_t*>(&h23),
                    *reinterpret_cast<uint32_t*>(&h45), *reinterpret_cast<uint32_t*>(&h67));
    lo = make_uint4(*reinterpret_cast<uint32_t*>(&l01), *reinterpret_cast<uint32_t*>(&l23),
                    *reinterpret_cast<uint32_t*>(&l45), *reinterpret_cast<uint32_t*>(&l67));
}

// ---------------- split-bf16 mma.sync GEMM ----------------
// C[M,N] = A[M,K] @ B^T, B stored [N,K] row-major (K-major).
// 128x128 block, BK=32, 256 threads (8 warps, 2x4), warp tile 64x32.
// EPI: C += gate[row]*gsum[col] + xres[row,col]
static constexpr int STAGE_BYTES = 32768;             // Ahi|Alo|Bhi|Blo each 8KB
static constexpr int GEMM_SMEM   = 2 * STAGE_BYTES;   // 64 KB

template <bool EPI>
__global__ __launch_bounds__(256, 1)
void mmagemm(const float* __restrict__ A, const float* __restrict__ B, float* __restrict__ C,
             int K, const float* __restrict__ gate, const float* __restrict__ gsum,
             const float* __restrict__ xres)
{
    extern __shared__ char smem[];
    const uint32_t su = smem_u32(smem);
    const int tid  = threadIdx.x;
    const int wid  = tid >> 5, lane = tid & 31;
    const int warpM = wid >> 2, warpN = wid & 3;       // 2 x 4 warps
    const int rowBase = blockIdx.y * 128;
    const int colBase = blockIdx.x * 128;
    const int ldcN = gridDim.x * 128;

    // loader: thread handles chunks tid and tid+256 of each matrix
    const int r0 = tid >> 2,         c0 = tid & 3;
    const int r1 = (tid + 256) >> 2, c1 = (tid + 256) & 3;
    const float* Ap0 = A + (size_t)(rowBase + r0) * K + c0 * 8;
    const float* Ap1 = A + (size_t)(rowBase + r1) * K + c1 * 8;
    const float* Bp0 = B + (size_t)(colBase + r0) * K + c0 * 8;
    const float* Bp1 = B + (size_t)(colBase + r1) * K + c1 * 8;

    float acc[4][4][4];
    #pragma unroll
    for (int i = 0; i < 4; i++)
        #pragma unroll
        for (int j = 0; j < 4; j++)
            #pragma unroll
            for (int k = 0; k < 4; k++) acc[i][j][k] = 0.0f;

    float4 pa[2][2], pb[2][2];
    const int KIT = K >> 5;

    // prefetch iter 0
    pa[0][0] = *reinterpret_cast<const float4*>(Ap0);
    pa[0][1] = *reinterpret_cast<const float4*>(Ap0 + 4);
    pa[1][0] = *reinterpret_cast<const float4*>(Ap1);
    pa[1][1] = *reinterpret_cast<const float4*>(Ap1 + 4);
    pb[0][0] = *reinterpret_cast<const float4*>(Bp0);
    pb[0][1] = *reinterpret_cast<const float4*>(Bp0 + 4);
    pb[1][0] = *reinterpret_cast<const float4*>(Bp1);
    pb[1][1] = *reinterpret_cast<const float4*>(Bp1 + 4);

    // lane-invariant ldmatrix helpers
    const int aRowL = warpM * 64 + (lane & 15);
    const int aCL   = lane >> 4;           // 0/1
    const int bRowL = warpN * 32 + (lane & 7);
    const int bCL   = (lane >> 3) & 1;     // 0/1 (lanes 16-31 replicate 0-15)

    for (int it = 0; it < KIT; ++it) {
        const int st = it & 1;
        const uint32_t sb = su + (uint32_t)st * STAGE_BYTES;

        // convert + store prefetched regs to smem
        {
            uint4 hi, lo;
            cvt_split(pa[0][0], pa[0][1], hi, lo);
            *reinterpret_cast<uint4*>((char*)nullptr + 0); // (no-op placeholder removed by compiler)
            *reinterpret_cast<uint4*>(smem + (sw_addr(sb, r0, c0) - su)) = hi;
            *reinterpret_cast<uint4*>(smem + (sw_addr(sb + 8192u, r0, c0) - su)) = lo;
            cvt_split(pa[1][0], pa[1][1], hi, lo);
            *reinterpret_cast<uint4*>(smem + (sw_addr(sb, r1, c1) - su)) = hi;
            *reinterpret_cast<uint4*>(smem + (sw_addr(sb + 8192u, r1, c1) - su)) = lo;
            cvt_split(pb[0][0], pb[0][1], hi, lo);
            *reinterpret_cast<uint4*>(smem + (sw_addr(sb + 16384u, r0, c0) - su)) = hi;
            *reinterpret_cast<uint4*>(smem + (sw_addr(sb + 24576u, r0, c0) - su)) = lo;
            cvt_split(pb[1][0], pb[1][1], hi, lo);
            *reinterpret_cast<uint4*>(smem + (sw_addr(sb + 16384u, r1, c1) - su)) = hi;
            *reinterpret_cast<uint4*>(smem + (sw_addr(sb + 24576u, r1, c1) - su)) = lo;
        }
        __syncthreads();

        // prefetch next iter
        if (it + 1 < KIT) {
            const int k0 = (it + 1) << 5;
            pa[0][0] = *reinterpret_cast<const float4*>(Ap0 + k0);
            pa[0][1] = *reinterpret_cast<const float4*>(Ap0 + k0 + 4);
            pa[1][0] = *reinterpret_cast<const float4*>(Ap1 + k0);
            pa[1][1] = *reinterpret_cast<const float4*>(Ap1 + k0 + 4);
            pb[0][0] = *reinterpret_cast<const float4*>(Bp0 + k0);
            pb[0][1] = *reinterpret_cast<const float4*>(Bp0 + k0 + 4);
            pb[1][0] = *reinterpret_cast<const float4*>(Bp1 + k0);
            pb[1][1] = *reinterpret_cast<const float4*>(Bp1 + k0 + 4);
        }

        // compute over this stage: two k16 halves
        #pragma unroll
        for (int kh = 0; kh < 2; kh++) {
            uint32_t ah[4][4], al[4][4], bh[4][2], bl[4][2];
            #pragma unroll
            for (int tm = 0; tm < 4; tm++) {
                ldsm_x4(ah[tm][0], ah[tm][1], ah[tm][2], ah[tm][3],
                        sw_addr(sb, aRowL + tm * 16, kh * 2 + aCL));
                ldsm_x4(al[tm][0], al[tm][1], al[tm][2], al[tm][3],
                        sw_addr(sb + 8192u, aRowL + tm * 16, kh * 2 + aCL));
            }
            #pragma unroll
            for (int tn = 0; tn < 4; tn++) {
                ldsm_x2(bh[tn][0], bh[tn][1],
                        sw_addr(sb + 16384u, bRowL + tn * 8, kh * 2 + bCL));
                ldsm_x2(bl[tn][0], bl[tn][1],
                        sw_addr(sb + 24576u, bRowL + tn * 8, kh * 2 + bCL));
            }
            #pragma unroll
            for (int tm = 0; tm < 4; tm++)
                #pragma unroll
                for (int tn = 0; tn < 4; tn++) {
                    mma_bf16(acc[tm][tn], ah[tm], bh[tn]);
                    mma_bf16(acc[tm][tn], ah[tm], bl[tn]);
                    mma_bf16(acc[tm][tn], al[tm], bh[tn]);
                }
        }
        __syncthreads();
    }

    // epilogue: direct stores (c0,c1)@row, (c2,c3)@row+8
    const int g  = lane >> 2;
    const int t4 = lane & 3;
    #pragma unroll
    for (int tm = 0; tm < 4; tm++) {
        const int row = rowBase + warpM * 64 + tm * 16 + g;
        #pragma unroll
        for (int tn = 0; tn < 4; tn++) {
            const int col = colBase + warpN * 32 + tn * 8 + t4 * 2;
            float v0 = acc[tm][tn][0], v1 = acc[tm][tn][1];
            float v2 = acc[tm][tn][2], v3 = acc[tm][tn][3];
            if (EPI) {
                const float gt0 = gate[row], gt8 = gate[row + 8];
                const float2 gs = *reinterpret_cast<const float2*>(gsum + col);
                const float2 x0 = *reinterpret_cast<const float2*>(
                    xres + (size_t)row * ldcN + col);
                const float2 x8 = *reinterpret_cast<const float2*>(
                    xres + (size_t)(row + 8) * ldcN + col);
                v0 += gt0 * gs.x + x0.x;  v1 += gt0 * gs.y + x0.y;
                v2 += gt8 * gs.x + x8.x;  v3 += gt8 * gs.y + x8.y;
            }
            *reinterpret_cast<float2*>(C + (size_t)row * ldcN + col) = make_float2(v0, v1);
            *reinterpret_cast<float2*>(C + (size_t)(row + 8) * ldcN + col) = make_float2(v2, v3);
        }
    }
}

// ---------------- transpose (32x32 tiles) ----------------
__global__ __launch_bounds__(256)
void transpose_kernel(const float* __restrict__ in, float* __restrict__ out, int R, int C)
{
    __shared__ float t[32][33];
    int bx = blockIdx.x * 32, by = blockIdx.y * 32;
    int x = threadIdx.x & 31, y0 = threadIdx.x >> 5;
    #pragma unroll
    for (int j = 0; j < 32; j += 8)
        t[y0 + j][x] = in[(size_t)(by + y0 + j) * C + bx + x];
    __syncthreads();
    #pragma unroll
    for (int j = 0; j < 32; j += 8)
        out[(size_t)(bx + y0 + j) * R + by + x] = t[x][y0 + j];
}

// ---------------- m = x @ Wm_w + b ----------------
__global__ __launch_bounds__(256)
void mvec_kernel(const float* __restrict__ x, const float* __restrict__ w,
                 const float* __restrict__ b, float* __restrict__ m)
{
    const int row  = blockIdx.x * 8 + (threadIdx.x >> 5);
    const int lane = threadIdx.x & 31;
    const float* xr = x + (size_t)row * DIM;
    float s = 0.0f;
    #pragma unroll
    for (int k = lane * 4; k < DIM; k += 128) {
        float4 xv = *reinterpret_cast<const float4*>(xr + k);
        float4 wv = *reinterpret_cast<const float4*>(w + k);
        s += xv.x * wv.x + xv.y * wv.y + xv.z * wv.z + xv.w * wv.w;
    }
    s = warpSum(s);
    if (lane == 0) m[row] = s + b[0];
}

// ---------------- column partial sums ----------------
__global__ void colsum_partial(const float* __restrict__ A, float* __restrict__ part)
{
    const int col   = blockIdx.x * blockDim.x + threadIdx.x;
    const int chunk = blockIdx.y;
    const int r0    = chunk * (NT / 32);
    float s = 0.0f;
    for (int r = 0; r < NT / 32; r++) s += A[(size_t)(r0 + r) * DIM + col];
    part[chunk * DIM + col] = s;
}
__global__ void colsum_final(const float* __restrict__ part, float* __restrict__ out, float scale)
{
    const int col = blockIdx.x * blockDim.x + threadIdx.x;
    float s = 0.0f;
    #pragma unroll
    for (int c = 0; c < 32; c++) s += part[c * DIM + col];
    out[col] = s * scale;
}

// ---------------- gate = softmax(m) over tokens ----------------
__global__ __launch_bounds__(1024)
void gate_kernel(const float* __restrict__ m, float* __restrict__ gate)
{
    __shared__ float red[32];
    const int tid = threadIdx.x, lane = tid & 31, wid = tid >> 5;
    float v[8];
    float vmax = -INFINITY;
    #pragma unroll
    for (int k = 0; k < 8; k++) { v[k] = m[tid + k * 1024]; vmax = fmaxf(vmax, v[k]); }
    vmax = warpMax(vmax);
    if (lane == 0) red[wid] = vmax;
    __syncthreads();
    float rmax = red[0];
    #pragma unroll
    for (int c = 1; c < 32; c++) rmax = fmaxf(rmax, red[c]);
    float s = 0.0f;
    #pragma unroll
    for (int k = 0; k < 8; k++) { v[k] = __expf(v[k] - rmax); s += v[k]; }
    s = warpSum(s);
    __syncthreads();
    if (lane == 0) red[wid] = s;
    __syncthreads();
    float tot = 0.0f;
    #pragma unroll
    for (int c = 0; c < 32; c++) tot += red[c];
    const float inv = 1.0f / tot;
    #pragma unroll
    for (int k = 0; k < 8; k++) gate[tid + k * 1024] = v[k] * inv;
}

// ---------------- center: qc=(qhat-mq)*c ; kc=khat-mk ----------------
__global__ __launch_bounds__(256)
void center_kernel(float* __restrict__ qc, float* __restrict__ kc,
                   const float* __restrict__ colred, const float* __restrict__ cptr)
{
    const float c = *cptr;
    const size_t i4   = (size_t)blockIdx.x * blockDim.x + threadIdx.x;
    const int    col4 = (int)(i4 & (DIM / 4 - 1));
    float4 mq = reinterpret_cast<const float4*>(colred)[col4];
    float4 mk = reinterpret_cast<const float4*>(colred + DIM)[col4];
    float4 q = reinterpret_cast<float4*>(qc)[i4];
    q.x = (q.x - mq.x) * c; q.y = (q.y - mq.y) * c;
    q.z = (q.z - mq.z) * c; q.w = (q.w - mq.w) * c;
    reinterpret_cast<float4*>(qc)[i4] = q;
    float4 k = reinterpret_cast<float4*>(kc)[i4];
    k.x -= mk.x; k.y -= mk.y; k.z -= mk.z; k.w -= mk.w;
    reinterpret_cast<float4*>(kc)[i4] = k;
}

// ---------------- row softmax of S in place ----------------
__global__ __launch_bounds__(256)
void softmax_kernel(float* __restrict__ S)
{
    __shared__ float buf[NT];
    __shared__ float red[8];
    const int tid = threadIdx.x, lane = tid & 31, wid = tid >> 5;
    float* Sr = S + (size_t)blockIdx.x * NT;

    float vmax = -INFINITY;
    #pragma unroll
    for (int k = 0; k < 8; k++) {
        int i = (tid + k * 256) * 4;
        float4 v = *reinterpret_cast<const float4*>(Sr + i);
        *reinterpret_cast<float4*>(buf + i) = v;
        vmax = fmaxf(vmax, fmaxf(fmaxf(v.x, v.y), fmaxf(v.z, v.w)));
    }
    vmax = warpMax(vmax);
    if (lane == 0) red[wid] = vmax;
    __syncthreads();
    float rmax = red[0];
    #pragma unroll
    for (int c = 1; c < 8; c++) rmax = fmaxf(rmax, red[c]);

    float ssum = 0.0f;
    #pragma unroll
    for (int k = 0; k < 8; k++) {
        int i = (tid + k * 256) * 4;
        float4 v = *reinterpret_cast<float4*>(buf + i);
        v.x = __expf(v.x - rmax); v.y = __expf(v.y - rmax);
        v.z = __expf(v.z - rmax); v.w = __expf(v.w - rmax);
        ssum += v.x + v.y + v.z + v.w;
        *reinterpret_cast<float4*>(buf + i) = v;
    }
    ssum = warpSum(ssum);
    __syncthreads();
    if (lane == 0) red[wid] = ssum;
    __syncthreads();
    float tot = 0.0f;
    #pragma unroll
    for (int c = 0; c < 8; c++) tot += red[c];
    const float inv = 1.0f / tot;
    #pragma unroll
    for (int k = 0; k < 8; k++) {
        int i = (tid + k * 256) * 4;
        float4 v = *reinterpret_cast<float4*>(buf + i);
        v.x *= inv; v.y *= inv; v.z *= inv; v.w *= inv;
        *reinterpret_cast<float4*>(Sr + i) = v;
    }
}

// ---------------- host launch ----------------
extern "C" void kernel_launch(void* const* d_in, const int* in_sizes, int n_in,
                              void* d_out, int out_size)
{
    const float* x    = (const float*)d_in[0];
    const float* Wq   = (const float*)d_in[1];
    const float* Wk   = (const float*)d_in[2];
    const float* Wg   = (const float*)d_in[3];
    const float* Wm_w = (const float*)d_in[4];
    const float* Wm_b = (const float*)d_in[5];
    const float* cs   = (const float*)d_in[6];
    float* out = (float*)d_out;

    float *qc, *kc, *g, *gT, *WT, *S, *part, *colred, *mv, *gate;
    cudaGetSymbolAddress((void**)&qc, d_qc);
    cudaGetSymbolAddress((void**)&kc, d_kc);
    cudaGetSymbolAddress((void**)&g,  d_g);
    cudaGetSymbolAddress((void**)&gT, d_gT);
    cudaGetSymbolAddress((void**)&WT, d_WT);
    cudaGetSymbolAddress((void**)&S,  d_S);
    cudaGetSymbolAddress((void**)&part, d_part);
    cudaGetSymbolAddress((void**)&colred, d_colred);
    cudaGetSymbolAddress((void**)&mv, d_m);
    cudaGetSymbolAddress((void**)&gate, d_gate);

    float* WqT = WT;
    float* WkT = WT + (size_t)DIM * DIM;
    float* WgT = WT + (size_t)2 * DIM * DIM;
    float* mq   = colred;
    float* mk   = colred + DIM;
    float* gsum = colred + 2 * DIM;

    cudaFuncSetAttribute(mmagemm<false>, cudaFuncAttributeMaxDynamicSharedMemorySize, GEMM_SMEM);
    cudaFuncSetAttribute(mmagemm<true>,  cudaFuncAttributeMaxDynamicSharedMemorySize, GEMM_SMEM);

    const dim3 gW(DIM / 32, DIM / 32);
    const dim3 gGT(DIM / 32, NT / 32);
    const dim3 gProj(DIM / 128, NT / 128);      // (8, 64)
    const dim3 gS(NT / 128, NT / 128);          // (64, 64)

    // 0) transpose weights to [N,K] K-major layout
    transpose_kernel<<<gW, 256>>>(Wq, WqT, DIM, DIM);
    transpose_kernel<<<gW, 256>>>(Wk, WkT, DIM, DIM);
    transpose_kernel<<<gW, 256>>>(Wg, WgT, DIM, DIM);

    // 1) projections (split-bf16 mma.sync)
    mmagemm<false><<<gProj, 256, GEMM_SMEM>>>(x, WqT, qc, DIM, nullptr, nullptr, nullptr);
    mmagemm<false><<<gProj, 256, GEMM_SMEM>>>(x, WkT, kc, DIM, nullptr, nullptr, nullptr);
    mmagemm<false><<<gProj, 256, GEMM_SMEM>>>(x, WgT, g,  DIM, nullptr, nullptr, nullptr);

    // 2) gate
    mvec_kernel<<<NT / 8, 256>>>(x, Wm_w, Wm_b, mv);
    gate_kernel<<<1, 1024>>>(mv, gate);

    // 3) column reductions
    colsum_partial<<<dim3(DIM / 256, 32), 256>>>(qc, part);
    colsum_final<<<DIM / 256, 256>>>(part, mq, 1.0f / NT);
    colsum_partial<<<dim3(DIM / 256, 32), 256>>>(kc, part);
    colsum_final<<<DIM / 256, 256>>>(part, mk, 1.0f / NT);
    colsum_partial<<<dim3(DIM / 256, 32), 256>>>(g, part);
    colsum_final<<<DIM / 256, 256>>>(part, gsum, 1.0f);

    // 4) center (fold c into q)
    center_kernel<<<(NT * (DIM / 4)) / 256, 256>>>(qc, kc, colred, cs);

    // 5) transpose g for the output GEMM
    transpose_kernel<<<gGT, 256>>>(g, gT, NT, DIM);

    // 6) S = qc @ kc^T
    mmagemm<false><<<gS, 256, GEMM_SMEM>>>(qc, kc, S, DIM, nullptr, nullptr, nullptr);

    // 7) row softmax in place
    softmax_kernel<<<NT, 256>>>(S);

    // 8) out = attn @ g + gate[i]*gsum[j] + x
    mmagemm<true><<<gProj, 256, GEMM_SMEM>>>(S, gT, out, NT, gate, gsum, x);
}

// round 5
// speedup vs baseline: 2.6760x; 1.2066x over previous
#include <cuda_runtime.h>
#include <cuda_bf16.h>
#include <cstdint>

#define NT 8192      // tokens
#define DIM 1024     // model dim

// ---------------- static device scratch (no allocs allowed) ----------------
__device__ float d_qhat[(size_t)NT * DIM];
__device__ float d_khat[(size_t)NT * DIM];
__device__ float d_g   [(size_t)NT * DIM];
__device__ float d_S   [(size_t)NT * NT];            // scores fp32 (256 MB)
__device__ __nv_bfloat16 d_Sh[(size_t)NT * NT];      // attn hi (128 MB)
__device__ __nv_bfloat16 d_Sl[(size_t)NT * NT];      // attn lo (128 MB)
__device__ __nv_bfloat16 d_xh[(size_t)NT * DIM];
__device__ __nv_bfloat16 d_xl[(size_t)NT * DIM];
__device__ __nv_bfloat16 d_qch[(size_t)NT * DIM];
__device__ __nv_bfloat16 d_qcl[(size_t)NT * DIM];
__device__ __nv_bfloat16 d_kch[(size_t)NT * DIM];
__device__ __nv_bfloat16 d_kcl[(size_t)NT * DIM];
__device__ __nv_bfloat16 d_gTh[(size_t)DIM * NT];
__device__ __nv_bfloat16 d_gTl[(size_t)DIM * NT];
__device__ __nv_bfloat16 d_WTh[(size_t)3 * DIM * DIM];
__device__ __nv_bfloat16 d_WTl[(size_t)3 * DIM * DIM];
__device__ float d_part[32 * DIM];
__device__ float d_colred[3 * DIM];                  // [mq | mk | gsum]
__device__ float d_m[NT];
__device__ float d_gate[NT];

// ---------------- small helpers ----------------
__device__ __forceinline__ float warpMax(float v) {
    #pragma unroll
    for (int o = 16; o > 0; o >>= 1) v = fmaxf(v, __shfl_xor_sync(0xffffffffu, v, o));
    return v;
}
__device__ __forceinline__ float warpSum(float v) {
    #pragma unroll
    for (int o = 16; o > 0; o >>= 1) v += __shfl_xor_sync(0xffffffffu, v, o);
    return v;
}
__device__ __forceinline__ uint32_t smem_u32(const void* p) {
    uint32_t a;
    asm("{ .reg .u64 t; cvta.to.shared.u64 t, %1; cvt.u32.u64 %0, t; }" : "=r"(a) : "l"(p));
    return a;
}
__device__ __forceinline__ void f2split(float v, __nv_bfloat16& h, __nv_bfloat16& l) {
    h = __float2bfloat16_rn(v);
    l = __float2bfloat16_rn(v - __bfloat162float(h));
}

// ---------------- mma.sync / ldmatrix / cp.async wrappers (base ISA) ----------------
__device__ __forceinline__ void ldsm_x4(uint32_t& r0, uint32_t& r1, uint32_t& r2, uint32_t& r3,
                                        uint32_t addr) {
    asm volatile("ldmatrix.sync.aligned.m8n8.x4.shared.b16 {%0,%1,%2,%3}, [%4];"
                 : "=r"(r0), "=r"(r1), "=r"(r2), "=r"(r3) : "r"(addr));
}
__device__ __forceinline__ void mma_bf16(float* c, const uint32_t* a, const uint32_t* b) {
    asm volatile("mma.sync.aligned.m16n8k16.row.col.f32.bf16.bf16.f32 "
                 "{%0,%1,%2,%3}, {%4,%5,%6,%7}, {%8,%9}, {%0,%1,%2,%3};"
                 : "+f"(c[0]), "+f"(c[1]), "+f"(c[2]), "+f"(c[3])
                 : "r"(a[0]), "r"(a[1]), "r"(a[2]), "r"(a[3]), "r"(b[0]), "r"(b[1]));
}
__device__ __forceinline__ void cp16(uint32_t dst, const void* src) {
    asm volatile("cp.async.cg.shared.global [%0], [%1], 16;" :: "r"(dst), "l"(src));
}
__device__ __forceinline__ void cp_commit() {
    asm volatile("cp.async.commit_group;" ::: "memory");
}
__device__ __forceinline__ void cp_wait2() {
    asm volatile("cp.async.wait_group 2;" ::: "memory");
}

// smem tile: 128 rows x 32 bf16 (64B/row); 16B unit c in 0..3, u = c ^ ((row>>1)&3)
__device__ __forceinline__ uint32_t sw_addr(uint32_t base, int row, int c) {
    return base + (uint32_t)(row * 64) + (uint32_t)((c ^ ((row >> 1) & 3)) << 4);
}

// ---------------- pipelined split-bf16 mma.sync GEMM ----------------
// C[M,N] = (Ah+Al)[M,K] @ (Bh+Bl)^T, B stored [N,K] row-major, bf16 hi/lo operands.
// 128x128 block, BK=32, 512 threads (16 warps, 4x4), warp tile 32x32, 4-stage cp.async.
static constexpr int STAGE_BYTES = 32768;            // Ah|Al|Bh|Bl each 8 KB
static constexpr int GEMM_STAGES = 4;
static constexpr int GEMM_SMEM   = GEMM_STAGES * STAGE_BYTES;  // 128 KB

template <bool EPI>
__global__ __launch_bounds__(512, 1)
void mmagemm(const __nv_bfloat16* __restrict__ Ah, const __nv_bfloat16* __restrict__ Al,
             const __nv_bfloat16* __restrict__ Bh, const __nv_bfloat16* __restrict__ Bl,
             float* __restrict__ C, int K,
             const float* __restrict__ gate, const float* __restrict__ gsum,
             const float* __restrict__ xres)
{
    extern __shared__ char smem[];
    const uint32_t su = smem_u32(smem);
    const int tid  = threadIdx.x;
    const int wid  = tid >> 5, lane = tid & 31;
    const int warpM = wid >> 2, warpN = wid & 3;     // 4 x 4 warps
    const int rowBase = blockIdx.y * 128;
    const int colBase = blockIdx.x * 128;
    const int ldcN = gridDim.x * 128;

    // loader: each thread does 1x16B per matrix per stage
    const int lr = tid >> 2, lc = tid & 3;           // row 0..127, unit 0..3
    const __nv_bfloat16* gAh = Ah + (size_t)(rowBase + lr) * K + lc * 8;
    const __nv_bfloat16* gAl = Al + (size_t)(rowBase + lr) * K + lc * 8;
    const __nv_bfloat16* gBh = Bh + (size_t)(colBase + lr) * K + lc * 8;
    const __nv_bfloat16* gBl = Bl + (size_t)(colBase + lr) * K + lc * 8;

    const int KIT = K >> 5;

    auto issue = [&](int stageIt) {
        const uint32_t sb = su + (uint32_t)(stageIt & 3) * STAGE_BYTES;
        const int k0 = stageIt << 5;
        cp16(sw_addr(sb,          lr, lc), gAh + k0);
        cp16(sw_addr(sb +  8192u, lr, lc), gAl + k0);
        cp16(sw_addr(sb + 16384u, lr, lc), gBh + k0);
        cp16(sw_addr(sb + 24576u, lr, lc), gBl + k0);
    };

    // prologue: stages 0..2
    #pragma unroll
    for (int p = 0; p < 3; p++) { issue(p); cp_commit(); }

    float acc[2][4][4];
    #pragma unroll
    for (int i = 0; i < 2; i++)
        #pragma unroll
        for (int j = 0; j < 4; j++)
            #pragma unroll
            for (int k = 0; k < 4; k++) acc[i][j][k] = 0.0f;

    // ldmatrix lane addressing
    const int aRow = warpM * 32 + (lane & 15);       // + tm*16
    const int aC   = lane >> 4;                      // 0/1
    const int bRow = warpN * 32 + (lane & 7) + ((lane >> 4) << 3);  // + pair*16
    const int bC   = (lane >> 3) & 1;                // 0/1

    for (int it = 0; it < KIT; ++it) {
        cp_wait2();
        __syncthreads();
        if (it + 3 < KIT) issue(it + 3);
        cp_commit();                                  // empty commit keeps count uniform

        const uint32_t sb = su + (uint32_t)(it & 3) * STAGE_BYTES;
        #pragma unroll
        for (int kh = 0; kh < 2; kh++) {
            uint32_t ah[2][4], al[2][4], bfh[4][2], bfl[4][2];
            #pragma unroll
            for (int tm = 0; tm < 2; tm++) {
                ldsm_x4(ah[tm][0], ah[tm][1], ah[tm][2], ah[tm][3],
                        sw_addr(sb, aRow + tm * 16, kh * 2 + aC));
                ldsm_x4(al[tm][0], al[tm][1], al[tm][2], al[tm][3],
                        sw_addr(sb + 8192u, aRow + tm * 16, kh * 2 + aC));
            }
            #pragma unroll
            for (int p = 0; p < 2; p++) {            // n-tile pairs (2p, 2p+1)
                ldsm_x4(bfh[2*p][0], bfh[2*p][1], bfh[2*p+1][0], bfh[2*p+1][1],
                        sw_addr(sb + 16384u, bRow + p * 16, kh * 2 + bC));
                ldsm_x4(bfl[2*p][0], bfl[2*p][1], bfl[2*p+1][0], bfl[2*p+1][1],
                        sw_addr(sb + 24576u, bRow + p * 16, kh * 2 + bC));
            }
            #pragma unroll
            for (int tm = 0; tm < 2; tm++)
                #pragma unroll
                for (int tn = 0; tn < 4; tn++) {
                    mma_bf16(acc[tm][tn], ah[tm], bfh[tn]);
                    mma_bf16(acc[tm][tn], ah[tm], bfl[tn]);
                    mma_bf16(acc[tm][tn], al[tm], bfh[tn]);
                }
        }
    }

    // epilogue: direct stores
    const int g  = lane >> 2;
    const int t4 = lane & 3;
    #pragma unroll
    for (int tm = 0; tm < 2; tm++) {
        const int row = rowBase + warpM * 32 + tm * 16 + g;
        #pragma unroll
        for (int tn = 0; tn < 4; tn++) {
            const int col = colBase + warpN * 32 + tn * 8 + t4 * 2;
            float v0 = acc[tm][tn][0], v1 = acc[tm][tn][1];
            float v2 = acc[tm][tn][2], v3 = acc[tm][tn][3];
            if (EPI) {
                const float gt0 = gate[row], gt8 = gate[row + 8];
                const float2 gs = *reinterpret_cast<const float2*>(gsum + col);
                const float2 x0 = *reinterpret_cast<const float2*>(
                    xres + (size_t)row * ldcN + col);
                const float2 x8 = *reinterpret_cast<const float2*>(
                    xres + (size_t)(row + 8) * ldcN + col);
                v0 += gt0 * gs.x + x0.x;  v1 += gt0 * gs.y + x0.y;
                v2 += gt8 * gs.x + x8.x;  v3 += gt8 * gs.y + x8.y;
            }
            *reinterpret_cast<float2*>(C + (size_t)row * ldcN + col) = make_float2(v0, v1);
            *reinterpret_cast<float2*>(C + (size_t)(row + 8) * ldcN + col) = make_float2(v2, v3);
        }
    }
}

// ---------------- elementwise split: fp32 -> bf16 hi/lo ----------------
__global__ __launch_bounds__(256)
void split_kernel(const float* __restrict__ in, __nv_bfloat16* __restrict__ hi,
                  __nv_bfloat16* __restrict__ lo)
{
    const size_t i = ((size_t)blockIdx.x * blockDim.x + threadIdx.x) * 4;
    float4 v = *reinterpret_cast<const float4*>(in + i);
    __nv_bfloat16 h[4], l[4];
    f2split(v.x, h[0], l[0]); f2split(v.y, h[1], l[1]);
    f2split(v.z, h[2], l[2]); f2split(v.w, h[3], l[3]);
    *reinterpret_cast<uint2*>(hi + i) = *reinterpret_cast<uint2*>(h);
    *reinterpret_cast<uint2*>(lo + i) = *reinterpret_cast<uint2*>(l);
}

// ---------------- transpose + split: fp32 [R,C] -> bf16 hi/lo [C,R] ----------------
__global__ __launch_bounds__(256)
void transpose_split_kernel(const float* __restrict__ in,
                            __nv_bfloat16* __restrict__ outH,
                            __nv_bfloat16* __restrict__ outL, int R, int C)
{
    __shared__ float t[32][33];
    int bx = blockIdx.x * 32, by = blockIdx.y * 32;
    int x = threadIdx.x & 31, y0 = threadIdx.x >> 5;
    #pragma unroll
    for (int j = 0; j < 32; j += 8)
        t[y0 + j][x] = in[(size_t)(by + y0 + j) * C + bx + x];
    __syncthreads();
    #pragma unroll
    for (int j = 0; j < 32; j += 8) {
        float v = t[x][y0 + j];
        __nv_bfloat16 h, l;
        f2split(v, h, l);
        size_t o = (size_t)(bx + y0 + j) * R + by + x;
        outH[o] = h;
        outL[o] = l;
    }
}

// ---------------- m = x @ Wm_w + b ----------------
__global__ __launch_bounds__(256)
void mvec_kernel(const float* __restrict__ x, const float* __restrict__ w,
                 const float* __restrict__ b, float* __restrict__ m)
{
    const int row  = blockIdx.x * 8 + (threadIdx.x >> 5);
    const int lane = threadIdx.x & 31;
    const float* xr = x + (size_t)row * DIM;
    float s = 0.0f;
    #pragma unroll
    for (int k = lane * 4; k < DIM; k += 128) {
        float4 xv = *reinterpret_cast<const float4*>(xr + k);
        float4 wv = *reinterpret_cast<const float4*>(w + k);
        s += xv.x * wv.x + xv.y * wv.y + xv.z * wv.z + xv.w * wv.w;
    }
    s = warpSum(s);
    if (lane == 0) m[row] = s + b[0];
}

// ---------------- column partial sums ----------------
__global__ void colsum_partial(const float* __restrict__ A, float* __restrict__ part)
{
    const int col   = blockIdx.x * blockDim.x + threadIdx.x;
    const int chunk = blockIdx.y;
    const int r0    = chunk * (NT / 32);
    float s = 0.0f;
    for (int r = 0; r < NT / 32; r++) s += A[(size_t)(r0 + r) * DIM + col];
    part[chunk * DIM + col] = s;
}
__global__ void colsum_final(const float* __restrict__ part, float* __restrict__ out, float scale)
{
    const int col = blockIdx.x * blockDim.x + threadIdx.x;
    float s = 0.0f;
    #pragma unroll
    for (int c = 0; c < 32; c++) s += part[c * DIM + col];
    out[col] = s * scale;
}

// ---------------- gate = softmax(m) over tokens ----------------
__global__ __launch_bounds__(1024)
void gate_kernel(const float* __restrict__ m, float* __restrict__ gate)
{
    __shared__ float red[32];
    const int tid = threadIdx.x, lane = tid & 31, wid = tid >> 5;
    float v[8];
    float vmax = -INFINITY;
    #pragma unroll
    for (int k = 0; k < 8; k++) { v[k] = m[tid + k * 1024]; vmax = fmaxf(vmax, v[k]); }
    vmax = warpMax(vmax);
    if (lane == 0) red[wid] = vmax;
    __syncthreads();
    float rmax = red[0];
    #pragma unroll
    for (int c = 1; c < 32; c++) rmax = fmaxf(rmax, red[c]);
    float s = 0.0f;
    #pragma unroll
    for (int k = 0; k < 8; k++) { v[k] = __expf(v[k] - rmax); s += v[k]; }
    s = warpSum(s);
    __syncthreads();
    if (lane == 0) red[wid] = s;
    __syncthreads();
    float tot = 0.0f;
    #pragma unroll
    for (int c = 0; c < 32; c++) tot += red[c];
    const float inv = 1.0f / tot;
    #pragma unroll
    for (int k = 0; k < 8; k++) gate[tid + k * 1024] = v[k] * inv;
}

// ---------------- center + split: qc=(qhat-mq)*c, kc=khat-mk -> bf16 hi/lo ----------------
__global__ __launch_bounds__(256)
void center_split_kernel(const float* __restrict__ qhat, const float* __restrict__ khat,
                         const float* __restrict__ colred, const float* __restrict__ cptr,
                         __nv_bfloat16* __restrict__ qch, __nv_bfloat16* __restrict__ qcl,
                         __nv_bfloat16* __restrict__ kch, __nv_bfloat16* __restrict__ kcl)
{
    const float c = *cptr;
    const size_t i4   = (size_t)blockIdx.x * blockDim.x + threadIdx.x;
    const size_t i    = i4 * 4;
    const int    col4 = (int)(i4 & (DIM / 4 - 1));
    float4 mq = reinterpret_cast<const float4*>(colred)[col4];
    float4 mk = reinterpret_cast<const float4*>(colred + DIM)[col4];
    float4 q = *reinterpret_cast<const float4*>(qhat + i);
    float4 k = *reinterpret_cast<const float4*>(khat + i);
    q.x = (q.x - mq.x) * c; q.y = (q.y - mq.y) * c;
    q.z = (q.z - mq.z) * c; q.w = (q.w - mq.w) * c;
    k.x -= mk.x; k.y -= mk.y; k.z -= mk.z; k.w -= mk.w;
    __nv_bfloat16 h[4], l[4];
    f2split(q.x, h[0], l[0]); f2split(q.y, h[1], l[1]);
    f2split(q.z, h[2], l[2]); f2split(q.w, h[3], l[3]);
    *reinterpret_cast<uint2*>(qch + i) = *reinterpret_cast<uint2*>(h);
    *reinterpret_cast<uint2*>(qcl + i) = *reinterpret_cast<uint2*>(l);
    f2split(k.x, h[0], l[0]); f2split(k.y, h[1], l[1]);
    f2split(k.z, h[2], l[2]); f2split(k.w, h[3], l[3]);
    *reinterpret_cast<uint2*>(kch + i) = *reinterpret_cast<uint2*>(h);
    *reinterpret_cast<uint2*>(kcl + i) = *reinterpret_cast<uint2*>(l);
}

// ---------------- row softmax of S -> bf16 hi/lo ----------------
__global__ __launch_bounds__(256)
void softmax_split_kernel(const float* __restrict__ S,
                          __nv_bfloat16* __restrict__ Sh, __nv_bfloat16* __restrict__ Sl)
{
    __shared__ float buf[NT];
    __shared__ float red[8];
    const int tid = threadIdx.x, lane = tid & 31, wid = tid >> 5;
    const float* Sr = S + (size_t)blockIdx.x * NT;
    __nv_bfloat16* ShR = Sh + (size_t)blockIdx.x * NT;
    __nv_bfloat16* SlR = Sl + (size_t)blockIdx.x * NT;

    float vmax = -INFINITY;
    #pragma unroll
    for (int k = 0; k < 8; k++) {
        int i = (tid + k * 256) * 4;
        float4 v = *reinterpret_cast<const float4*>(Sr + i);
        *reinterpret_cast<float4*>(buf + i) = v;
        vmax = fmaxf(vmax, fmaxf(fmaxf(v.x, v.y), fmaxf(v.z, v.w)));
    }
    vmax = warpMax(vmax);
    if (lane == 0) red[wid] = vmax;
    __syncthreads();
    float rmax = red[0];
    #pragma unroll
    for (int c = 1; c < 8; c++) rmax = fmaxf(rmax, red[c]);

    float ssum = 0.0f;
    #pragma unroll
    for (int k = 0; k < 8; k++) {
        int i = (tid + k * 256) * 4;
        float4 v = *reinterpret_cast<float4*>(buf + i);
        v.x = __expf(v.x - rmax); v.y = __expf(v.y - rmax);
        v.z = __expf(v.z - rmax); v.w = __expf(v.w - rmax);
        ssum += v.x + v.y + v.z + v.w;
        *reinterpret_cast<float4*>(buf + i) = v;
    }
    ssum = warpSum(ssum);
    __syncthreads();
    if (lane == 0) red[wid] = ssum;
    __syncthreads();
    float tot = 0.0f;
    #pragma unroll
    for (int c = 0; c < 8; c++) tot += red[c];
    const float inv = 1.0f / tot;
    #pragma unroll
    for (int k = 0; k < 8; k++) {
        int i = (tid + k * 256) * 4;
        float4 v = *reinterpret_cast<float4*>(buf + i);
        v.x *= inv; v.y *= inv; v.z *= inv; v.w *= inv;
        __nv_bfloat16 h[4], l[4];
        f2split(v.x, h[0], l[0]); f2split(v.y, h[1], l[1]);
        f2split(v.z, h[2], l[2]); f2split(v.w, h[3], l[3]);
        *reinterpret_cast<uint2*>(ShR + i) = *reinterpret_cast<uint2*>(h);
        *reinterpret_cast<uint2*>(SlR + i) = *reinterpret_cast<uint2*>(l);
    }
}

// ---------------- host launch ----------------
extern "C" void kernel_launch(void* const* d_in, const int* in_sizes, int n_in,
                              void* d_out, int out_size)
{
    const float* x    = (const float*)d_in[0];
    const float* Wq   = (const float*)d_in[1];
    const float* Wk   = (const float*)d_in[2];
    const float* Wg   = (const float*)d_in[3];
    const float* Wm_w = (const float*)d_in[4];
    const float* Wm_b = (const float*)d_in[5];
    const float* cs   = (const float*)d_in[6];
    float* out = (float*)d_out;

    float *qhat, *khat, *g, *S, *part, *colred, *mv, *gate;
    __nv_bfloat16 *Sh, *Sl, *xh, *xl, *qch, *qcl, *kch, *kcl, *gTh, *gTl, *WTh, *WTl;
    cudaGetSymbolAddress((void**)&qhat, d_qhat);
    cudaGetSymbolAddress((void**)&khat, d_khat);
    cudaGetSymbolAddress((void**)&g,    d_g);
    cudaGetSymbolAddress((void**)&S,    d_S);
    cudaGetSymbolAddress((void**)&Sh,   d_Sh);
    cudaGetSymbolAddress((void**)&Sl,   d_Sl);
    cudaGetSymbolAddress((void**)&xh,   d_xh);
    cudaGetSymbolAddress((void**)&xl,   d_xl);
    cudaGetSymbolAddress((void**)&qch,  d_qch);
    cudaGetSymbolAddress((void**)&qcl,  d_qcl);
    cudaGetSymbolAddress((void**)&kch,  d_kch);
    cudaGetSymbolAddress((void**)&kcl,  d_kcl);
    cudaGetSymbolAddress((void**)&gTh,  d_gTh);
    cudaGetSymbolAddress((void**)&gTl,  d_gTl);
    cudaGetSymbolAddress((void**)&WTh,  d_WTh);
    cudaGetSymbolAddress((void**)&WTl,  d_WTl);
    cudaGetSymbolAddress((void**)&part, d_part);
    cudaGetSymbolAddress((void**)&colred, d_colred);
    cudaGetSymbolAddress((void**)&mv,   d_m);
    cudaGetSymbolAddress((void**)&gate, d_gate);

    __nv_bfloat16* WqTh = WTh;
    __nv_bfloat16* WqTl = WTl;
    __nv_bfloat16* WkTh = WTh + (size_t)DIM * DIM;
    __nv_bfloat16* WkTl = WTl + (size_t)DIM * DIM;
    __nv_bfloat16* WgTh = WTh + (size_t)2 * DIM * DIM;
    __nv_bfloat16* WgTl = WTl + (size_t)2 * DIM * DIM;
    float* mq   = colred;
    float* mk   = colred + DIM;
    float* gsum = colred + 2 * DIM;

    cudaFuncSetAttribute(mmagemm<false>, cudaFuncAttributeMaxDynamicSharedMemorySize, GEMM_SMEM);
    cudaFuncSetAttribute(mmagemm<true>,  cudaFuncAttributeMaxDynamicSharedMemorySize, GEMM_SMEM);

    const dim3 gW(DIM / 32, DIM / 32);
    const dim3 gGT(DIM / 32, NT / 32);
    const dim3 gProj(DIM / 128, NT / 128);      // (8, 64)
    const dim3 gS(NT / 128, NT / 128);          // (64, 64)

    // 0) prepasses: weights -> transposed bf16 hi/lo ; x -> bf16 hi/lo
    transpose_split_kernel<<<gW, 256>>>(Wq, WqTh, WqTl, DIM, DIM);
    transpose_split_kernel<<<gW, 256>>>(Wk, WkTh, WkTl, DIM, DIM);
    transpose_split_kernel<<<gW, 256>>>(Wg, WgTh, WgTl, DIM, DIM);
    split_kernel<<<(NT * DIM / 4) / 256, 256>>>(x, xh, xl);

    // 1) projections
    mmagemm<false><<<gProj, 512, GEMM_SMEM>>>(xh, xl, WqTh, WqTl, qhat, DIM, nullptr, nullptr, nullptr);
    mmagemm<false><<<gProj, 512, GEMM_SMEM>>>(xh, xl, WkTh, WkTl, khat, DIM, nullptr, nullptr, nullptr);
    mmagemm<false><<<gProj, 512, GEMM_SMEM>>>(xh, xl, WgTh, WgTl, g,    DIM, nullptr, nullptr, nullptr);

    // 2) gate
    mvec_kernel<<<NT / 8, 256>>>(x, Wm_w, Wm_b, mv);
    gate_kernel<<<1, 1024>>>(mv, gate);

    // 3) column reductions
    colsum_partial<<<dim3(DIM / 256, 32), 256>>>(qhat, part);
    colsum_final<<<DIM / 256, 256>>>(part, mq, 1.0f / NT);
    colsum_partial<<<dim3(DIM / 256, 32), 256>>>(khat, part);
    colsum_final<<<DIM / 256, 256>>>(part, mk, 1.0f / NT);
    colsum_partial<<<dim3(DIM / 256, 32), 256>>>(g, part);
    colsum_final<<<DIM / 256, 256>>>(part, gsum, 1.0f);

    // 4) center + split to bf16 hi/lo (fold c into q)
    center_split_kernel<<<(NT * (DIM / 4)) / 256, 256>>>(qhat, khat, colred, cs,
                                                         qch, qcl, kch, kcl);

    // 5) transpose + split g -> gT bf16 hi/lo
    transpose_split_kernel<<<gGT, 256>>>(g, gTh, gTl, NT, DIM);

    // 6) S = qc @ kc^T (fp32 out)
    mmagemm<false><<<gS, 512, GEMM_SMEM>>>(qch, qcl, kch, kcl, S, DIM, nullptr, nullptr, nullptr);

    // 7) row softmax -> attn bf16 hi/lo
    softmax_split_kernel<<<NT, 256>>>(S, Sh, Sl);

    // 8) out = attn @ g + gate[i]*gsum[j] + x
    mmagemm<true><<<gProj, 512, GEMM_SMEM>>>(Sh, Sl, gTh, gTl, out, NT, gate, gsum, x);
}

// round 6
// speedup vs baseline: 3.0180x; 1.1278x over previous
#include <cuda_runtime.h>
#include <cuda_bf16.h>
#include <cstdint>

#define NT 8192      // tokens
#define DIM 1024     // model dim

// ---------------- static device scratch (no allocs allowed) ----------------
__device__ float d_qhat[(size_t)NT * DIM];
__device__ float d_khat[(size_t)NT * DIM];
__device__ float d_g   [(size_t)NT * DIM];
__device__ float d_S   [(size_t)NT * NT];            // scores fp32 (256 MB)
__device__ __nv_bfloat16 d_Sh[(size_t)NT * NT];      // attn hi (128 MB)
__device__ __nv_bfloat16 d_Sl[(size_t)NT * NT];      // attn lo (128 MB)
__device__ __nv_bfloat16 d_xh[(size_t)NT * DIM];
__device__ __nv_bfloat16 d_xl[(size_t)NT * DIM];
__device__ __nv_bfloat16 d_qch[(size_t)NT * DIM];
__device__ __nv_bfloat16 d_qcl[(size_t)NT * DIM];
__device__ __nv_bfloat16 d_kch[(size_t)NT * DIM];
__device__ __nv_bfloat16 d_kcl[(size_t)NT * DIM];
__device__ __nv_bfloat16 d_gTh[(size_t)DIM * NT];
__device__ __nv_bfloat16 d_gTl[(size_t)DIM * NT];
__device__ __nv_bfloat16 d_WTh[(size_t)3 * DIM * DIM];
__device__ __nv_bfloat16 d_WTl[(size_t)3 * DIM * DIM];
__device__ float d_part[32 * DIM];
__device__ float d_colred[3 * DIM];                  // [mq | mk | gsum]
__device__ float d_m[NT];
__device__ float d_gate[NT];

// ---------------- small helpers ----------------
__device__ __forceinline__ float warpMax(float v) {
    #pragma unroll
    for (int o = 16; o > 0; o >>= 1) v = fmaxf(v, __shfl_xor_sync(0xffffffffu, v, o));
    return v;
}
__device__ __forceinline__ float warpSum(float v) {
    #pragma unroll
    for (int o = 16; o > 0; o >>= 1) v += __shfl_xor_sync(0xffffffffu, v, o);
    return v;
}
__device__ __forceinline__ uint32_t smem_u32(const void* p) {
    uint32_t a;
    asm("{ .reg .u64 t; cvta.to.shared.u64 t, %1; cvt.u32.u64 %0, t; }" : "=r"(a) : "l"(p));
    return a;
}
__device__ __forceinline__ void f2split(float v, __nv_bfloat16& h, __nv_bfloat16& l) {
    h = __float2bfloat16_rn(v);
    l = __float2bfloat16_rn(v - __bfloat162float(h));
}

// ---------------- mma.sync / ldmatrix / cp.async wrappers (base ISA) ----------------
__device__ __forceinline__ void ldsm_x4(uint32_t& r0, uint32_t& r1, uint32_t& r2, uint32_t& r3,
                                        uint32_t addr) {
    asm volatile("ldmatrix.sync.aligned.m8n8.x4.shared.b16 {%0,%1,%2,%3}, [%4];"
                 : "=r"(r0), "=r"(r1), "=r"(r2), "=r"(r3) : "r"(addr));
}
__device__ __forceinline__ void mma_bf16(float* c, const uint32_t* a, const uint32_t* b) {
    asm volatile("mma.sync.aligned.m16n8k16.row.col.f32.bf16.bf16.f32 "
                 "{%0,%1,%2,%3}, {%4,%5,%6,%7}, {%8,%9}, {%0,%1,%2,%3};"
                 : "+f"(c[0]), "+f"(c[1]), "+f"(c[2]), "+f"(c[3])
                 : "r"(a[0]), "r"(a[1]), "r"(a[2]), "r"(a[3]), "r"(b[0]), "r"(b[1]));
}
__device__ __forceinline__ void cp16(uint32_t dst, const void* src) {
    asm volatile("cp.async.cg.shared.global [%0], [%1], 16;" :: "r"(dst), "l"(src));
}
__device__ __forceinline__ void cp_commit() {
    asm volatile("cp.async.commit_group;" ::: "memory");
}
__device__ __forceinline__ void cp_wait1() {
    asm volatile("cp.async.wait_group 1;" ::: "memory");
}

// smem tile: 128 rows x 64 bf16 (128B/row); 16B unit c in 0..7, u = c ^ (row&7)
__device__ __forceinline__ uint32_t sw_addr(uint32_t base, int row, int c) {
    return base + (uint32_t)(row * 128) + (uint32_t)((c ^ (row & 7)) << 4);
}

// ---------------- pipelined split-bf16 mma.sync GEMM ----------------
// C[M,N] = (Ah+Al)[M,K] @ (Bh+Bl)^T, B stored [N,K] row-major, bf16 hi/lo operands.
// 128x128 block, BK=64, 512 threads (16 warps, 4x4), warp tile 32x32, 3-stage cp.async.
static constexpr int STAGE_BYTES = 65536;            // Ah|Al|Bh|Bl each 16 KB
static constexpr int GEMM_STAGES = 3;
static constexpr int GEMM_SMEM   = GEMM_STAGES * STAGE_BYTES;  // 192 KB

template <bool EPI>
__global__ __launch_bounds__(512, 1)
void mmagemm(const __nv_bfloat16* __restrict__ Ah, const __nv_bfloat16* __restrict__ Al,
             const __nv_bfloat16* __restrict__ Bh, const __nv_bfloat16* __restrict__ Bl,
             float* __restrict__ C, int K,
             const float* __restrict__ gate, const float* __restrict__ gsum,
             const float* __restrict__ xres)
{
    extern __shared__ char smem[];
    const uint32_t su = smem_u32(smem);
    const int tid  = threadIdx.x;
    const int wid  = tid >> 5, lane = tid & 31;
    const int warpM = wid >> 2, warpN = wid & 3;     // 4 x 4 warps
    const int rowBase = blockIdx.y * 128;
    const int colBase = blockIdx.x * 128;
    const int ldcN = gridDim.x * 128;

    // loader: 512 threads; each does 2x16B per matrix per stage (rows lr and lr+64)
    const int lr = tid >> 3, lc = tid & 7;           // row 0..63, unit 0..7
    const __nv_bfloat16* gAh = Ah + (size_t)(rowBase + lr) * K + lc * 8;
    const __nv_bfloat16* gAl = Al + (size_t)(rowBase + lr) * K + lc * 8;
    const __nv_bfloat16* gBh = Bh + (size_t)(colBase + lr) * K + lc * 8;
    const __nv_bfloat16* gBl = Bl + (size_t)(colBase + lr) * K + lc * 8;
    const size_t rstep = (size_t)64 * K;

    const int KIT = K >> 6;

    auto issue = [&](int stage) {
        const uint32_t sb = su + (uint32_t)(stage % 3) * STAGE_BYTES;
        const int k0 = stage << 6;
        cp16(sw_addr(sb,          lr,      lc), gAh + k0);
        cp16(sw_addr(sb,          lr + 64, lc), gAh + rstep + k0);
        cp16(sw_addr(sb + 16384u, lr,      lc), gAl + k0);
        cp16(sw_addr(sb + 16384u, lr + 64, lc), gAl + rstep + k0);
        cp16(sw_addr(sb + 32768u, lr,      lc), gBh + k0);
        cp16(sw_addr(sb + 32768u, lr + 64, lc), gBh + rstep + k0);
        cp16(sw_addr(sb + 49152u, lr,      lc), gBl + k0);
        cp16(sw_addr(sb + 49152u, lr + 64, lc), gBl + rstep + k0);
    };

    // prologue: stages 0..1
    issue(0); cp_commit();
    if (KIT > 1) issue(1);
    cp_commit();

    float acc[2][4][4];
    #pragma unroll
    for (int i = 0; i < 2; i++)
        #pragma unroll
        for (int j = 0; j < 4; j++)
            #pragma unroll
            for (int k = 0; k < 4; k++) acc[i][j][k] = 0.0f;

    // ldmatrix lane addressing
    const int aRow = warpM * 32 + (lane & 15);       // + tm*16
    const int aC   = lane >> 4;                      // 0/1
    const int bRow = warpN * 32 + (lane & 7) + ((lane >> 4) << 3);  // + pair*16
    const int bC   = (lane >> 3) & 1;                // 0/1

    for (int it = 0; it < KIT; ++it) {
        cp_wait1();
        __syncthreads();
        if (it + 2 < KIT) issue(it + 2);
        cp_commit();                                  // empty commit keeps count uniform

        const uint32_t sb = su + (uint32_t)(it % 3) * STAGE_BYTES;
        #pragma unroll
        for (int kh = 0; kh < 4; kh++) {
            uint32_t ah[2][4], al[2][4], bfh[4][2], bfl[4][2];
            #pragma unroll
            for (int tm = 0; tm < 2; tm++) {
                ldsm_x4(ah[tm][0], ah[tm][1], ah[tm][2], ah[tm][3],
                        sw_addr(sb, aRow + tm * 16, kh * 2 + aC));
                ldsm_x4(al[tm][0], al[tm][1], al[tm][2], al[tm][3],
                        sw_addr(sb + 16384u, aRow + tm * 16, kh * 2 + aC));
            }
            #pragma unroll
            for (int p = 0; p < 2; p++) {            // n-tile pairs (2p, 2p+1)
                ldsm_x4(bfh[2*p][0], bfh[2*p][1], bfh[2*p+1][0], bfh[2*p+1][1],
                        sw_addr(sb + 32768u, bRow + p * 16, kh * 2 + bC));
                ldsm_x4(bfl[2*p][0], bfl[2*p][1], bfl[2*p+1][0], bfl[2*p+1][1],
                        sw_addr(sb + 49152u, bRow + p * 16, kh * 2 + bC));
            }
            #pragma unroll
            for (int tm = 0; tm < 2; tm++)
                #pragma unroll
                for (int tn = 0; tn < 4; tn++) {
                    mma_bf16(acc[tm][tn], ah[tm], bfh[tn]);
                    mma_bf16(acc[tm][tn], ah[tm], bfl[tn]);
                    mma_bf16(acc[tm][tn], al[tm], bfh[tn]);
                }
        }
    }

    // epilogue: direct stores
    const int g  = lane >> 2;
    const int t4 = lane & 3;
    #pragma unroll
    for (int tm = 0; tm < 2; tm++) {
        const int row = rowBase + warpM * 32 + tm * 16 + g;
        #pragma unroll
        for (int tn = 0; tn < 4; tn++) {
            const int col = colBase + warpN * 32 + tn * 8 + t4 * 2;
            float v0 = acc[tm][tn][0], v1 = acc[tm][tn][1];
            float v2 = acc[tm][tn][2], v3 = acc[tm][tn][3];
            if (EPI) {
                const float gt0 = gate[row], gt8 = gate[row + 8];
                const float2 gs = *reinterpret_cast<const float2*>(gsum + col);
                const float2 x0 = *reinterpret_cast<const float2*>(
                    xres + (size_t)row * ldcN + col);
                const float2 x8 = *reinterpret_cast<const float2*>(
                    xres + (size_t)(row + 8) * ldcN + col);
                v0 += gt0 * gs.x + x0.x;  v1 += gt0 * gs.y + x0.y;
                v2 += gt8 * gs.x + x8.x;  v3 += gt8 * gs.y + x8.y;
            }
            *reinterpret_cast<float2*>(C + (size_t)row * ldcN + col) = make_float2(v0, v1);
            *reinterpret_cast<float2*>(C + (size_t)(row + 8) * ldcN + col) = make_float2(v2, v3);
        }
    }
}

// ---------------- elementwise split: fp32 -> bf16 hi/lo ----------------
__global__ __launch_bounds__(256)
void split_kernel(const float* __restrict__ in, __nv_bfloat16* __restrict__ hi,
                  __nv_bfloat16* __restrict__ lo)
{
    const size_t i = ((size_t)blockIdx.x * blockDim.x + threadIdx.x) * 4;
    float4 v = *reinterpret_cast<const float4*>(in + i);
    __nv_bfloat16 h[4], l[4];
    f2split(v.x, h[0], l[0]); f2split(v.y, h[1], l[1]);
    f2split(v.z, h[2], l[2]); f2split(v.w, h[3], l[3]);
    *reinterpret_cast<uint2*>(hi + i) = *reinterpret_cast<uint2*>(h);
    *reinterpret_cast<uint2*>(lo + i) = *reinterpret_cast<uint2*>(l);
}

// ---------------- transpose + split: fp32 [R,C] -> bf16 hi/lo [C,R] ----------------
__global__ __launch_bounds__(256)
void transpose_split_kernel(const float* __restrict__ in,
                            __nv_bfloat16* __restrict__ outH,
                            __nv_bfloat16* __restrict__ outL, int R, int C)
{
    __shared__ float t[32][33];
    int bx = blockIdx.x * 32, by = blockIdx.y * 32;
    int x = threadIdx.x & 31, y0 = threadIdx.x >> 5;
    #pragma unroll
    for (int j = 0; j < 32; j += 8)
        t[y0 + j][x] = in[(size_t)(by + y0 + j) * C + bx + x];
    __syncthreads();
    #pragma unroll
    for (int j = 0; j < 32; j += 8) {
        float v = t[x][y0 + j];
        __nv_bfloat16 h, l;
        f2split(v, h, l);
        size_t o = (size_t)(bx + y0 + j) * R + by + x;
        outH[o] = h;
        outL[o] = l;
    }
}

// ---------------- m = x @ Wm_w + b ----------------
__global__ __launch_bounds__(256)
void mvec_kernel(const float* __restrict__ x, const float* __restrict__ w,
                 const float* __restrict__ b, float* __restrict__ m)
{
    const int row  = blockIdx.x * 8 + (threadIdx.x >> 5);
    const int lane = threadIdx.x & 31;
    const float* xr = x + (size_t)row * DIM;
    float s = 0.0f;
    #pragma unroll
    for (int k = lane * 4; k < DIM; k += 128) {
        float4 xv = *reinterpret_cast<const float4*>(xr + k);
        float4 wv = *reinterpret_cast<const float4*>(w + k);
        s += xv.x * wv.x + xv.y * wv.y + xv.z * wv.z + xv.w * wv.w;
    }
    s = warpSum(s);
    if (lane == 0) m[row] = s + b[0];
}

// ---------------- column partial sums ----------------
__global__ void colsum_partial(const float* __restrict__ A, float* __restrict__ part)
{
    const int col   = blockIdx.x * blockDim.x + threadIdx.x;
    const int chunk = blockIdx.y;
    const int r0    = chunk * (NT / 32);
    float s = 0.0f;
    for (int r = 0; r < NT / 32; r++) s += A[(size_t)(r0 + r) * DIM + col];
    part[chunk * DIM + col] = s;
}
__global__ void colsum_final(const float* __restrict__ part, float* __restrict__ out, float scale)
{
    const int col = blockIdx.x * blockDim.x + threadIdx.x;
    float s = 0.0f;
    #pragma unroll
    for (int c = 0; c < 32; c++) s += part[c * DIM + col];
    out[col] = s * scale;
}

// ---------------- gate = softmax(m) over tokens ----------------
__global__ __launch_bounds__(1024)
void gate_kernel(const float* __restrict__ m, float* __restrict__ gate)
{
    __shared__ float red[32];
    const int tid = threadIdx.x, lane = tid & 31, wid = tid >> 5;
    float v[8];
    float vmax = -INFINITY;
    #pragma unroll
    for (int k = 0; k < 8; k++) { v[k] = m[tid + k * 1024]; vmax = fmaxf(vmax, v[k]); }
    vmax = warpMax(vmax);
    if (lane == 0) red[wid] = vmax;
    __syncthreads();
    float rmax = red[0];
    #pragma unroll
    for (int c = 1; c < 32; c++) rmax = fmaxf(rmax, red[c]);
    float s = 0.0f;
    #pragma unroll
    for (int k = 0; k < 8; k++) { v[k] = __expf(v[k] - rmax); s += v[k]; }
    s = warpSum(s);
    __syncthreads();
    if (lane == 0) red[wid] = s;
    __syncthreads();
    float tot = 0.0f;
    #pragma unroll
    for (int c = 0; c < 32; c++) tot += red[c];
    const float inv = 1.0f / tot;
    #pragma unroll
    for (int k = 0; k < 8; k++) gate[tid + k * 1024] = v[k] * inv;
}

// ---------------- center + split: qc=(qhat-mq)*c, kc=khat-mk -> bf16 hi/lo ----------------
__global__ __launch_bounds__(256)
void center_split_kernel(const float* __restrict__ qhat, const float* __restrict__ khat,
                         const float* __restrict__ colred, const float* __restrict__ cptr,
                         __nv_bfloat16* __restrict__ qch, __nv_bfloat16* __restrict__ qcl,
                         __nv_bfloat16* __restrict__ kch, __nv_bfloat16* __restrict__ kcl)
{
    const float c = *cptr;
    const size_t i4   = (size_t)blockIdx.x * blockDim.x + threadIdx.x;
    const size_t i    = i4 * 4;
    const int    col4 = (int)(i4 & (DIM / 4 - 1));
    float4 mq = reinterpret_cast<const float4*>(colred)[col4];
    float4 mk = reinterpret_cast<const float4*>(colred + DIM)[col4];
    float4 q = *reinterpret_cast<const float4*>(qhat + i);
    float4 k = *reinterpret_cast<const float4*>(khat + i);
    q.x = (q.x - mq.x) * c; q.y = (q.y - mq.y) * c;
    q.z = (q.z - mq.z) * c; q.w = (q.w - mq.w) * c;
    k.x -= mk.x; k.y -= mk.y; k.z -= mk.z; k.w -= mk.w;
    __nv_bfloat16 h[4], l[4];
    f2split(q.x, h[0], l[0]); f2split(q.y, h[1], l[1]);
    f2split(q.z, h[2], l[2]); f2split(q.w, h[3], l[3]);
    *reinterpret_cast<uint2*>(qch + i) = *reinterpret_cast<uint2*>(h);
    *reinterpret_cast<uint2*>(qcl + i) = *reinterpret_cast<uint2*>(l);
    f2split(k.x, h[0], l[0]); f2split(k.y, h[1], l[1]);
    f2split(k.z, h[2], l[2]); f2split(k.w, h[3], l[3]);
    *reinterpret_cast<uint2*>(kch + i) = *reinterpret_cast<uint2*>(h);
    *reinterpret_cast<uint2*>(kcl + i) = *reinterpret_cast<uint2*>(l);
}

// ---------------- row softmax of S -> bf16 hi/lo ----------------
__global__ __launch_bounds__(256)
void softmax_split_kernel(const float* __restrict__ S,
                          __nv_bfloat16* __restrict__ Sh, __nv_bfloat16* __restrict__ Sl)
{
    __shared__ float buf[NT];
    __shared__ float red[8];
    const int tid = threadIdx.x, lane = tid & 31, wid = tid >> 5;
    const float* Sr = S + (size_t)blockIdx.x * NT;
    __nv_bfloat16* ShR = Sh + (size_t)blockIdx.x * NT;
    __nv_bfloat16* SlR = Sl + (size_t)blockIdx.x * NT;

    float vmax = -INFINITY;
    #pragma unroll
    for (int k = 0; k < 8; k++) {
        int i = (tid + k * 256) * 4;
        float4 v = *reinterpret_cast<const float4*>(Sr + i);
        *reinterpret_cast<float4*>(buf + i) = v;
        vmax = fmaxf(vmax, fmaxf(fmaxf(v.x, v.y), fmaxf(v.z, v.w)));
    }
    vmax = warpMax(vmax);
    if (lane == 0) red[wid] = vmax;
    __syncthreads();
    float rmax = red[0];
    #pragma unroll
    for (int c = 1; c < 8; c++) rmax = fmaxf(rmax, red[c]);

    float ssum = 0.0f;
    #pragma unroll
    for (int k = 0; k < 8; k++) {
        int i = (tid + k * 256) * 4;
        float4 v = *reinterpret_cast<float4*>(buf + i);
        v.x = __expf(v.x - rmax); v.y = __expf(v.y - rmax);
        v.z = __expf(v.z - rmax); v.w = __expf(v.w - rmax);
        ssum += v.x + v.y + v.z + v.w;
        *reinterpret_cast<float4*>(buf + i) = v;
    }
    ssum = warpSum(ssum);
    __syncthreads();
    if (lane == 0) red[wid] = ssum;
    __syncthreads();
    float tot = 0.0f;
    #pragma unroll
    for (int c = 0; c < 8; c++) tot += red[c];
    const float inv = 1.0f / tot;
    #pragma unroll
    for (int k = 0; k < 8; k++) {
        int i = (tid + k * 256) * 4;
        float4 v = *reinterpret_cast<float4*>(buf + i);
        v.x *= inv; v.y *= inv; v.z *= inv; v.w *= inv;
        __nv_bfloat16 h[4], l[4];
        f2split(v.x, h[0], l[0]); f2split(v.y, h[1], l[1]);
        f2split(v.z, h[2], l[2]); f2split(v.w, h[3], l[3]);
        *reinterpret_cast<uint2*>(ShR + i) = *reinterpret_cast<uint2*>(h);
        *reinterpret_cast<uint2*>(SlR + i) = *reinterpret_cast<uint2*>(l);
    }
}

// ---------------- host launch ----------------
extern "C" void kernel_launch(void* const* d_in, const int* in_sizes, int n_in,
                              void* d_out, int out_size)
{
    const float* x    = (const float*)d_in[0];
    const float* Wq   = (const float*)d_in[1];
    const float* Wk   = (const float*)d_in[2];
    const float* Wg   = (const float*)d_in[3];
    const float* Wm_w = (const float*)d_in[4];
    const float* Wm_b = (const float*)d_in[5];
    const float* cs   = (const float*)d_in[6];
    float* out = (float*)d_out;

    float *qhat, *khat, *g, *S, *part, *colred, *mv, *gate;
    __nv_bfloat16 *Sh, *Sl, *xh, *xl, *qch, *qcl, *kch, *kcl, *gTh, *gTl, *WTh, *WTl;
    cudaGetSymbolAddress((void**)&qhat, d_qhat);
    cudaGetSymbolAddress((void**)&khat, d_khat);
    cudaGetSymbolAddress((void**)&g,    d_g);
    cudaGetSymbolAddress((void**)&S,    d_S);
    cudaGetSymbolAddress((void**)&Sh,   d_Sh);
    cudaGetSymbolAddress((void**)&Sl,   d_Sl);
    cudaGetSymbolAddress((void**)&xh,   d_xh);
    cudaGetSymbolAddress((void**)&xl,   d_xl);
    cudaGetSymbolAddress((void**)&qch,  d_qch);
    cudaGetSymbolAddress((void**)&qcl,  d_qcl);
    cudaGetSymbolAddress((void**)&kch,  d_kch);
    cudaGetSymbolAddress((void**)&kcl,  d_kcl);
    cudaGetSymbolAddress((void**)&gTh,  d_gTh);
    cudaGetSymbolAddress((void**)&gTl,  d_gTl);
    cudaGetSymbolAddress((void**)&WTh,  d_WTh);
    cudaGetSymbolAddress((void**)&WTl,  d_WTl);
    cudaGetSymbolAddress((void**)&part, d_part);
    cudaGetSymbolAddress((void**)&colred, d_colred);
    cudaGetSymbolAddress((void**)&mv,   d_m);
    cudaGetSymbolAddress((void**)&gate, d_gate);

    __nv_bfloat16* WqTh = WTh;
    __nv_bfloat16* WqTl = WTl;
    __nv_bfloat16* WkTh = WTh + (size_t)DIM * DIM;
    __nv_bfloat16* WkTl = WTl + (size_t)DIM * DIM;
    __nv_bfloat16* WgTh = WTh + (size_t)2 * DIM * DIM;
    __nv_bfloat16* WgTl = WTl + (size_t)2 * DIM * DIM;
    float* mq   = colred;
    float* mk   = colred + DIM;
    float* gsum = colred + 2 * DIM;

    cudaFuncSetAttribute(mmagemm<false>, cudaFuncAttributeMaxDynamicSharedMemorySize, GEMM_SMEM);
    cudaFuncSetAttribute(mmagemm<true>,  cudaFuncAttributeMaxDynamicSharedMemorySize, GEMM_SMEM);

    const dim3 gW(DIM / 32, DIM / 32);
    const dim3 gGT(DIM / 32, NT / 32);
    const dim3 gProj(DIM / 128, NT / 128);      // (8, 64)
    const dim3 gS(NT / 128, NT / 128);          // (64, 64)

    // 0) prepasses: weights -> transposed bf16 hi/lo ; x -> bf16 hi/lo
    transpose_split_kernel<<<gW, 256>>>(Wq, WqTh, WqTl, DIM, DIM);
    transpose_split_kernel<<<gW, 256>>>(Wk, WkTh, WkTl, DIM, DIM);
    transpose_split_kernel<<<gW, 256>>>(Wg, WgTh, WgTl, DIM, DIM);
    split_kernel<<<(NT * DIM / 4) / 256, 256>>>(x, xh, xl);

    // 1) projections
    mmagemm<false><<<gProj, 512, GEMM_SMEM>>>(xh, xl, WqTh, WqTl, qhat, DIM, nullptr, nullptr, nullptr);
    mmagemm<false><<<gProj, 512, GEMM_SMEM>>>(xh, xl, WkTh, WkTl, khat, DIM, nullptr, nullptr, nullptr);
    mmagemm<false><<<gProj, 512, GEMM_SMEM>>>(xh, xl, WgTh, WgTl, g,    DIM, nullptr, nullptr, nullptr);

    // 2) gate
    mvec_kernel<<<NT / 8, 256>>>(x, Wm_w, Wm_b, mv);
    gate_kernel<<<1, 1024>>>(mv, gate);

    // 3) column reductions
    colsum_partial<<<dim3(DIM / 256, 32), 256>>>(qhat, part);
    colsum_final<<<DIM / 256, 256>>>(part, mq, 1.0f / NT);
    colsum_partial<<<dim3(DIM / 256, 32), 256>>>(khat, part);
    colsum_final<<<DIM / 256, 256>>>(part, mk, 1.0f / NT);
    colsum_partial<<<dim3(DIM / 256, 32), 256>>>(g, part);
    colsum_final<<<DIM / 256, 256>>>(part, gsum, 1.0f);

    // 4) center + split to bf16 hi/lo (fold c into q)
    center_split_kernel<<<(NT * (DIM / 4)) / 256, 256>>>(qhat, khat, colred, cs,
                                                         qch, qcl, kch, kcl);

    // 5) transpose + split g -> gT bf16 hi/lo
    transpose_split_kernel<<<gGT, 256>>>(g, gTh, gTl, NT, DIM);

    // 6) S = qc @ kc^T (fp32 out)
    mmagemm<false><<<gS, 512, GEMM_SMEM>>>(qch, qcl, kch, kcl, S, DIM, nullptr, nullptr, nullptr);

    // 7) row softmax -> attn bf16 hi/lo
    softmax_split_kernel<<<NT, 256>>>(S, Sh, Sl);

    // 8) out = attn @ g + gate[i]*gsum[j] + x
    mmagemm<true><<<gProj, 512, GEMM_SMEM>>>(Sh, Sl, gTh, gTl, out, NT, gate, gsum, x);
}